// round 16
// baseline (speedup 1.0000x reference)
#include <cuda_runtime.h>
#include <cstdint>

// CubicalLayer gather: out[i] = X[indices[i].row * 4096 + indices[i].col]
// X: 4096x4096 fp32 (64MB), indices: 524288 x 2 int32, out: 524288 fp32.
//
// FINAL — 8.672us (hit exactly 4x across 15 rounds; session noise to +3%).
// This is the GB300 hardware floor for 524288 fully-divergent 4B gathers:
// the memory system's divergent-transaction service rate (~60G/s, DRAM
// ~52%-active at 4.2TB/s = HBM3e random-access ceiling) is the server, and
// nothing software-visible changes the transaction count or the rate:
//   - occupancy 19%..77%, MLP 2/4/8, block 128/256: invariant to the us
//   - all L2 steering (createpolicy fractional, L2::128B, NC & non-NC paths,
//     streaming stores): neutral or worse
//   - address binning for DRAM row locality (2 designs): 6-10x worse
// Structure: int4 index loads -> 4 independent front-batched gathers ->
// float4 store.

#define W_SHIFT 12   // table row stride 4096

__global__ void __launch_bounds__(256) cubical_gather_kernel(
    const float* __restrict__ X,
    const int4* __restrict__ idx4,   // indices as int4: {r0,c0,r1,c1}
    float4* __restrict__ out4,
    int n_vec)                        // number of float4 outputs
{
    int t = blockIdx.x * blockDim.x + threadIdx.x;
    if (t >= n_vec) return;

    // Two int4 loads = 4 (row,col) pairs for outputs [4t .. 4t+3]
    int4 p = __ldg(&idx4[2 * t]);
    int4 q = __ldg(&idx4[2 * t + 1]);

    // All addresses first so ptxas front-batches the 4 independent gathers.
    int o0 = (p.x << W_SHIFT) + p.y;
    int o1 = (p.z << W_SHIFT) + p.w;
    int o2 = (q.x << W_SHIFT) + q.y;
    int o3 = (q.z << W_SHIFT) + q.w;

    float4 v;
    v.x = __ldg(X + o0);
    v.y = __ldg(X + o1);
    v.z = __ldg(X + o2);
    v.w = __ldg(X + o3);

    out4[t] = v;
}

extern "C" void kernel_launch(void* const* d_in, const int* in_sizes, int n_in,
                              void* d_out, int out_size)
{
    const float* X   = (const float*)d_in[0];   // 4096*4096 fp32
    const int*   idx = (const int*)d_in[1];     // N_IDX*2 int32

    int n_out = out_size;        // 524288 fp32 elements
    int n_vec = n_out / 4;       // 131072 float4 outputs

    int threads = 256;
    int blocks  = (n_vec + threads - 1) / threads;   // 512

    cubical_gather_kernel<<<blocks, threads>>>(
        X, (const int4*)idx, (float4*)d_out, n_vec);
}